// round 13
// baseline (speedup 1.0000x reference)
#include <cuda_runtime.h>
#include <math.h>

#define QN 1024
#define KN 1024
#define DN 64
#define BHN 64
#define QSCALE 0.125f

#define LA 36   // [p][32k] tile stride (banks: 4p+c all distinct)
#define LB 72   // [k][64n] natural tile stride (banks: 8k+n all distinct)

// q packed as [i][bh][d], pre-scaled
__device__ float g_qp[(size_t)QN * BHN * DN];

// ---------------------------------------------------------------------------
__device__ __forceinline__ unsigned cvt_tf32(float x) {
    unsigned u;
    asm("cvt.rna.tf32.f32 %0, %1;" : "=r"(u) : "f"(x));
    return u;
}
// split x into hi(tf32) and lo(tf32 of residual), as raw bits
__device__ __forceinline__ void split_bits(float x, unsigned& h, unsigned& l) {
    h = cvt_tf32(x);
    float hf = __uint_as_float(h);
    l = cvt_tf32(x - hf);
}

// triangular decode: t -> (ti, tj) with tj <= ti
__device__ __forceinline__ void tri_decode(int t, int& ti, int& tj) {
    float f = sqrtf(8.f * (float)t + 1.f);
    ti = (int)((f - 1.f) * 0.5f);
    while ((ti + 1) * (ti + 2) / 2 <= t) ++ti;
    while (ti * (ti + 1) / 2 > t) --ti;
    tj = t - ti * (ti + 1) / 2;
}

// Fill A-type tile [64 rows][32 cols], stride LA, fp32 (split happens at load)
__device__ __forceinline__ void fillA(float* dst, const float* src,
                                      size_t rs, float scale, int tid) {
#pragma unroll
    for (int ph = 0; ph < 2; ++ph) {
        int idx = tid + ph * 256;
        int p = idx >> 3, c4 = idx & 7;
        float4 v = *(const float4*)(src + (size_t)p * rs + c4 * 4);
        v.x *= scale; v.y *= scale; v.z *= scale; v.w *= scale;
        *(float4*)(dst + p * LA + c4 * 4) = v;
    }
}

// Fill B-natural tile [32 rows(k)][64 cols(n)], stride LB, fp32
__device__ __forceinline__ void fillB(float* dst, const float* src,
                                      size_t rs, int tid) {
#pragma unroll
    for (int ph = 0; ph < 2; ++ph) {
        int idx = tid + ph * 256;
        int p = idx >> 4, c4 = idx & 15;
        float4 v = *(const float4*)(src + (size_t)p * rs + c4 * 4);
        *(float4*)(dst + p * LB + c4 * 4) = v;
    }
}

// ---------------------------------------------------------------------------
// frag loaders: fp32 smem -> hi/lo tf32 register fragments
// ---------------------------------------------------------------------------
__device__ __forceinline__ void ldAfrag_hl(const float* t, int m0, int k0,
                                           int lane, unsigned ah[4],
                                           unsigned al[4]) {
    const float* b = t + (m0 + (lane >> 2)) * LA + k0 + (lane & 3);
    split_bits(b[0],           ah[0], al[0]);
    split_bits(b[8 * LA],      ah[1], al[1]);
    split_bits(b[4],           ah[2], al[2]);
    split_bits(b[8 * LA + 4],  ah[3], al[3]);
}
__device__ __forceinline__ void ldBnk_hl(const float* t, int n0, int k0,
                                         int lane, unsigned bh2[2],
                                         unsigned bl2[2]) {
    const float* b = t + (n0 + (lane >> 2)) * LA + k0 + (lane & 3);
    split_bits(b[0], bh2[0], bl2[0]);
    split_bits(b[4], bh2[1], bl2[1]);
}
__device__ __forceinline__ void ldBkn_hl(const float* t, int n0, int k0,
                                         int lane, unsigned bh2[2],
                                         unsigned bl2[2]) {
    const float* b = t + (k0 + (lane & 3)) * LB + n0 + (lane >> 2);
    split_bits(b[0],        bh2[0], bl2[0]);
    split_bits(b[4 * LB],   bh2[1], bl2[1]);
}

__device__ __forceinline__ void mma8(float d[4], const unsigned a[4],
                                     const unsigned b[2]) {
    asm volatile(
        "mma.sync.aligned.m16n8k8.row.col.f32.tf32.tf32.f32 "
        "{%0,%1,%2,%3},{%4,%5,%6,%7},{%8,%9},{%0,%1,%2,%3};"
        : "+f"(d[0]), "+f"(d[1]), "+f"(d[2]), "+f"(d[3])
        : "r"(a[0]), "r"(a[1]), "r"(a[2]), "r"(a[3]), "r"(b[0]), "r"(b[1]));
}

// 3xtf32 over one k32 chunk; A [m][k] stride LA, B [n][k] stride LA
__device__ __forceinline__ void gemm_nk(const float* As, const float* Bs,
                                        float acc[4][4], int wm, int wn,
                                        int lane) {
    int m0 = wm * 16, n0 = wn * 32;
#pragma unroll
    for (int k0 = 0; k0 < 32; k0 += 8) {
        unsigned ah[4], al[4];
        ldAfrag_hl(As, m0, k0, lane, ah, al);
#pragma unroll
        for (int g = 0; g < 4; ++g) {
            unsigned bh2[2], bl2[2];
            ldBnk_hl(Bs, n0 + 8 * g, k0, lane, bh2, bl2);
            mma8(acc[g], ah, bh2);
            mma8(acc[g], ah, bl2);
            mma8(acc[g], al, bh2);
        }
    }
}

// 3xtf32 over one k32 chunk; A [m][k] stride LA, B natural [k][n] stride LB
__device__ __forceinline__ void gemm_kn(const float* As, const float* Bs,
                                        float acc[4][4], int wm, int wn,
                                        int lane) {
    int m0 = wm * 16, n0 = wn * 32;
#pragma unroll
    for (int k0 = 0; k0 < 32; k0 += 8) {
        unsigned ah[4], al[4];
        ldAfrag_hl(As, m0, k0, lane, ah, al);
#pragma unroll
        for (int g = 0; g < 4; ++g) {
            unsigned bh2[2], bl2[2];
            ldBkn_hl(Bs, n0 + 8 * g, k0, lane, bh2, bl2);
            mma8(acc[g], ah, bh2);
            mma8(acc[g], ah, bl2);
            mma8(acc[g], al, bh2);
        }
    }
}

// ---------------------------------------------------------------------------
__global__ __launch_bounds__(256) void k_pack(const float* __restrict__ q) {
    int i = blockIdx.x, tid = threadIdx.x;
#pragma unroll
    for (int p = 0; p < 4; ++p) {
        int idx = tid + p * 256;
        int bh = idx >> 4, c4 = idx & 15;
        float4 v = *(const float4*)(q + ((size_t)bh * QN + i) * DN + c4 * 4);
        v.x *= QSCALE; v.y *= QSCALE; v.z *= QSCALE; v.w *= QSCALE;
        *(float4*)(g_qp + (size_t)i * (BHN * DN) + bh * DN + c4 * 4) = v;
    }
}

// ---------------------------------------------------------------------------
// G1: score = q_s . k  (exactly the 136 causal tiles per bh)
// ---------------------------------------------------------------------------
__global__ __launch_bounds__(256, 6) void k_score_qk(const float* __restrict__ q,
                                                     const float* __restrict__ kk,
                                                     float* __restrict__ alpha) {
    int ti, tj;
    tri_decode(blockIdx.x, ti, tj);
    int bh = blockIdx.y;
    __shared__ alignas(16) float As[64 * LA];
    __shared__ alignas(16) float Bs[64 * LA];
    int tid = threadIdx.x, lane = tid & 31, w = tid >> 5;
    int wm = w & 3, wn = w >> 2;
    float acc[4][4] = {};
#pragma unroll
    for (int kc = 0; kc < 2; ++kc) {
        fillA(As, q + ((size_t)bh * QN + ti * 64) * DN + kc * 32, DN, QSCALE, tid);
        fillA(Bs, kk + ((size_t)bh * KN + tj * 64) * DN + kc * 32, DN, 1.f, tid);
        __syncthreads();
        gemm_nk(As, Bs, acc, wm, wn, lane);
        __syncthreads();
    }
    int r0 = ti * 64 + wm * 16 + (lane >> 2);
    int c0 = tj * 64 + wn * 32 + 2 * (lane & 3);
    float* base = alpha + (size_t)bh * QN * KN;
#pragma unroll
    for (int g = 0; g < 4; ++g) {
        *(float2*)(base + (size_t)r0 * KN + c0 + 8 * g) = make_float2(acc[g][0], acc[g][1]);
        *(float2*)(base + (size_t)(r0 + 8) * KN + c0 + 8 * g) = make_float2(acc[g][2], acc[g][3]);
    }
}

// ---------------------------------------------------------------------------
// G2: score += q_s . rpe_q[i]  (per-i GEMM over bh; only live tiles)
// ---------------------------------------------------------------------------
__global__ __launch_bounds__(256, 6) void k_score_rpe(const float* __restrict__ rq,
                                                      float* __restrict__ alpha) {
    int t = blockIdx.x;
    int gi, tj;
    tri_decode(t >> 6, gi, tj);
    int i = gi * 64 + (t & 63);
    __shared__ alignas(16) float As[64 * LA];
    __shared__ alignas(16) float Bs[64 * LA];
    int tid = threadIdx.x, lane = tid & 31, w = tid >> 5;
    int wm = w & 3, wn = w >> 2;
    float acc[4][4] = {};
#pragma unroll
    for (int kc = 0; kc < 2; ++kc) {
        fillA(As, g_qp + (size_t)i * (BHN * DN) + kc * 32, DN, 1.f, tid);
        fillA(Bs, rq + ((size_t)i * KN + tj * 64) * DN + kc * 32, DN, 1.f, tid);
        __syncthreads();
        gemm_nk(As, Bs, acc, wm, wn, lane);
        __syncthreads();
    }
    int bh0 = wm * 16 + (lane >> 2);
    int j0 = tj * 64 + wn * 32 + 2 * (lane & 3);
#pragma unroll
    for (int g = 0; g < 4; ++g) {
        float2* p0 = (float2*)(alpha + ((size_t)bh0 * QN + i) * KN + j0 + 8 * g);
        float2* p1 = (float2*)(alpha + ((size_t)(bh0 + 8) * QN + i) * KN + j0 + 8 * g);
        float2 v0 = *p0, v1 = *p1;
        v0.x += acc[g][0]; v0.y += acc[g][1];
        v1.x += acc[g][2]; v1.y += acc[g][3];
        *p0 = v0; *p1 = v1;
    }
}

// ---------------------------------------------------------------------------
// softmax: warp-per-row, causal, fully unrolled register pipeline.
// ---------------------------------------------------------------------------
__global__ __launch_bounds__(256) void k_softmax(float* __restrict__ alpha) {
    int bh = blockIdx.x;
    int i = blockIdx.y * 8 + (threadIdx.x >> 5);
    int lane = threadIdx.x & 31;
    float4* row = (float4*)(alpha + ((size_t)bh * QN + i) * KN);

    int nq4 = (i >> 2) + 1;  // float4s containing causal elements

    float4 e[8];
    float vmax = -INFINITY;
#pragma unroll
    for (int it = 0; it < 8; ++it) {
        int j4 = lane + it * 32;
        float4 s = make_float4(-INFINITY, -INFINITY, -INFINITY, -INFINITY);
        if (j4 < nq4) {
            s = row[j4];
            int j = j4 * 4;
            if (j + 1 > i) s.y = -INFINITY;
            if (j + 2 > i) s.z = -INFINITY;
            if (j + 3 > i) s.w = -INFINITY;
        }
        e[it] = s;
        vmax = fmaxf(vmax, fmaxf(fmaxf(s.x, s.y), fmaxf(s.z, s.w)));
    }
#pragma unroll
    for (int o = 16; o > 0; o >>= 1)
        vmax = fmaxf(vmax, __shfl_xor_sync(0xffffffffu, vmax, o));

    float lsum = 0.f;
#pragma unroll
    for (int it = 0; it < 8; ++it) {
        float4 s = e[it];
        float4 ev;
        ev.x = (s.x == -INFINITY) ? 0.f : __expf(s.x - vmax);
        ev.y = (s.y == -INFINITY) ? 0.f : __expf(s.y - vmax);
        ev.z = (s.z == -INFINITY) ? 0.f : __expf(s.z - vmax);
        ev.w = (s.w == -INFINITY) ? 0.f : __expf(s.w - vmax);
        e[it] = ev;
        lsum += ev.x + ev.y + ev.z + ev.w;
    }
#pragma unroll
    for (int o = 16; o > 0; o >>= 1)
        lsum += __shfl_xor_sync(0xffffffffu, lsum, o);
    float inv = (lsum > 0.f) ? (1.f / lsum) : 0.f;

#pragma unroll
    for (int it = 0; it < 8; ++it) {
        int j4 = lane + it * 32;
        float4 ev = e[it];
        row[j4] = make_float4(ev.x * inv, ev.y * inv, ev.z * inv, ev.w * inv);
    }
}

// ---------------------------------------------------------------------------
// G3: ctx = alpha @ v   (per (ti,bh); causal k-loop in 32-chunks)
// ---------------------------------------------------------------------------
__global__ __launch_bounds__(256, 6) void k_ctx_v(const float* __restrict__ alpha,
                                                  const float* __restrict__ v,
                                                  float* __restrict__ ctx) {
    int ti = blockIdx.x, bh = blockIdx.y;
    __shared__ alignas(16) float As[64 * LA];
    __shared__ alignas(16) float Bs[32 * LB];
    int tid = threadIdx.x, lane = tid & 31, w = tid >> 5;
    int wm = w & 3, wn = w >> 2;
    float acc[4][4] = {};
    int nch = (ti + 1) * 2;
    for (int kc = 0; kc < nch; ++kc) {
        fillA(As, alpha + ((size_t)bh * QN + ti * 64) * KN + kc * 32, KN, 1.f, tid);
        fillB(Bs, v + ((size_t)bh * KN + kc * 32) * DN, DN, tid);
        __syncthreads();
        gemm_kn(As, Bs, acc, wm, wn, lane);
        __syncthreads();
    }
    int r0 = ti * 64 + wm * 16 + (lane >> 2);
    int c0 = wn * 32 + 2 * (lane & 3);
    float* base = ctx + (size_t)bh * QN * DN;
#pragma unroll
    for (int g = 0; g < 4; ++g) {
        *(float2*)(base + (size_t)r0 * DN + c0 + 8 * g) = make_float2(acc[g][0], acc[g][1]);
        *(float2*)(base + (size_t)(r0 + 8) * DN + c0 + 8 * g) = make_float2(acc[g][2], acc[g][3]);
    }
}

// ---------------------------------------------------------------------------
// G4: ctx[bh,i,:] += sum_j alpha[bh,i,j] * rpe_v[i,j,:]  (per-i over bh)
// ---------------------------------------------------------------------------
__global__ __launch_bounds__(256, 6) void k_ctx_rpe(const float* __restrict__ alpha,
                                                    const float* __restrict__ rv,
                                                    float* __restrict__ ctx) {
    int i = (QN - 1) - blockIdx.x;
    int nch = (i >> 5) + 1;
    __shared__ alignas(16) float As[64 * LA];
    __shared__ alignas(16) float Bs[32 * LB];
    int tid = threadIdx.x, lane = tid & 31, w = tid >> 5;
    int wm = w & 3, wn = w >> 2;
    float acc[4][4] = {};
    for (int kc = 0; kc < nch; ++kc) {
        fillA(As, alpha + (size_t)i * KN + kc * 32, (size_t)QN * KN, 1.f, tid);
        fillB(Bs, rv + ((size_t)i * KN + kc * 32) * DN, DN, tid);
        __syncthreads();
        gemm_kn(As, Bs, acc, wm, wn, lane);
        __syncthreads();
    }
    int bh0 = wm * 16 + (lane >> 2);
    int c0 = wn * 32 + 2 * (lane & 3);
#pragma unroll
    for (int g = 0; g < 4; ++g) {
        float2* p0 = (float2*)(ctx + ((size_t)bh0 * QN + i) * DN + c0 + 8 * g);
        float2* p1 = (float2*)(ctx + ((size_t)(bh0 + 8) * QN + i) * DN + c0 + 8 * g);
        float2 v0 = *p0, v1 = *p1;
        v0.x += acc[g][0]; v0.y += acc[g][1];
        v1.x += acc[g][2]; v1.y += acc[g][3];
        *p0 = v0; *p1 = v1;
    }
}

// ---------------------------------------------------------------------------
extern "C" void kernel_launch(void* const* d_in, const int* in_sizes, int n_in,
                              void* d_out, int out_size) {
    const float* q    = (const float*)d_in[0];
    const float* kk   = (const float*)d_in[1];
    const float* v    = (const float*)d_in[2];
    const float* rq   = (const float*)d_in[4];
    const float* rv   = (const float*)d_in[5];

    float* ctx   = (float*)d_out;
    float* alpha = ctx + (size_t)BHN * QN * DN;

    k_pack<<<QN, 256>>>(q);
    k_score_qk<<<dim3(136, BHN), 256>>>(q, kk, alpha);
    k_score_rpe<<<136 * 64, 256>>>(rq, alpha);
    k_softmax<<<dim3(BHN, QN / 8), 256>>>(alpha);
    k_ctx_v<<<dim3(16, BHN), 256>>>(alpha, v, ctx);
    k_ctx_rpe<<<QN, 256>>>(alpha, rv, ctx);
}

// round 14
// speedup vs baseline: 1.1884x; 1.1884x over previous
#include <cuda_runtime.h>
#include <math.h>

#define QN 1024
#define KN 1024
#define DN 64
#define BHN 64
#define QSCALE 0.125f

#define LA 36   // [p][32k] tile stride (banks: 4p+c all distinct)
#define LB 72   // [k][64n] natural tile stride (banks: 8k+n all distinct)

// q packed as [i][bh][d], pre-scaled
__device__ float g_qp[(size_t)QN * BHN * DN];

// ---------------------------------------------------------------------------
__device__ __forceinline__ unsigned cvt_tf32(float x) {
    unsigned u;
    asm("cvt.rna.tf32.f32 %0, %1;" : "=r"(u) : "f"(x));
    return u;
}
__device__ __forceinline__ void split2(float x, float& h, float& l) {
    unsigned uh = cvt_tf32(x);
    h = __uint_as_float(uh);
    l = __uint_as_float(cvt_tf32(x - h));
}

// triangular decode: t -> (ti, tj) with tj <= ti
__device__ __forceinline__ void tri_decode(int t, int& ti, int& tj) {
    float f = sqrtf(8.f * (float)t + 1.f);
    ti = (int)((f - 1.f) * 0.5f);
    while ((ti + 1) * (ti + 2) / 2 <= t) ++ti;
    while (ti * (ti + 1) / 2 > t) --ti;
    tj = t - ti * (ti + 1) / 2;
}

// ---------------------------------------------------------------------------
// tile fills (128 threads), hi/lo split done HERE (once per smem byte)
// ---------------------------------------------------------------------------
// A-type tile [64 rows][32 cols], stride LA
__device__ __forceinline__ void fillA(float* hi, float* lo, const float* src,
                                      size_t rs, float scale, int tid) {
#pragma unroll
    for (int ph = 0; ph < 4; ++ph) {
        int idx = tid + ph * 128;
        int p = idx >> 3, c4 = idx & 7;
        float4 v = *(const float4*)(src + (size_t)p * rs + c4 * 4);
        float4 h, l;
        split2(v.x * scale, h.x, l.x);
        split2(v.y * scale, h.y, l.y);
        split2(v.z * scale, h.z, l.z);
        split2(v.w * scale, h.w, l.w);
        *(float4*)(hi + p * LA + c4 * 4) = h;
        *(float4*)(lo + p * LA + c4 * 4) = l;
    }
}

// B-natural tile [32 rows(k)][64 cols(n)], stride LB
__device__ __forceinline__ void fillB(float* hi, float* lo, const float* src,
                                      size_t rs, int tid) {
#pragma unroll
    for (int ph = 0; ph < 4; ++ph) {
        int idx = tid + ph * 128;
        int p = idx >> 4, c4 = idx & 15;
        float4 v = *(const float4*)(src + (size_t)p * rs + c4 * 4);
        float4 h, l;
        split2(v.x, h.x, l.x);
        split2(v.y, h.y, l.y);
        split2(v.z, h.z, l.z);
        split2(v.w, h.w, l.w);
        *(float4*)(hi + p * LB + c4 * 4) = h;
        *(float4*)(lo + p * LB + c4 * 4) = l;
    }
}

// ---------------------------------------------------------------------------
// fragment loaders
// ---------------------------------------------------------------------------
__device__ __forceinline__ void ldAfrag(const float* t, int m0, int k0,
                                        int lane, unsigned a[4]) {
    const float* b = t + (m0 + (lane >> 2)) * LA + k0 + (lane & 3);
    a[0] = __float_as_uint(b[0]);
    a[1] = __float_as_uint(b[8 * LA]);
    a[2] = __float_as_uint(b[4]);
    a[3] = __float_as_uint(b[8 * LA + 4]);
}
__device__ __forceinline__ void ldBnk(const float* t, int n0, int k0,
                                      int lane, unsigned b2[2]) {
    const float* b = t + (n0 + (lane >> 2)) * LA + k0 + (lane & 3);
    b2[0] = __float_as_uint(b[0]);
    b2[1] = __float_as_uint(b[4]);
}
__device__ __forceinline__ void ldBkn(const float* t, int n0, int k0,
                                      int lane, unsigned b2[2]) {
    const float* b = t + (k0 + (lane & 3)) * LB + n0 + (lane >> 2);
    b2[0] = __float_as_uint(b[0]);
    b2[1] = __float_as_uint(b[4 * LB]);
}

__device__ __forceinline__ void mma8(float d[4], const unsigned a[4],
                                     const unsigned b[2]) {
    asm volatile(
        "mma.sync.aligned.m16n8k8.row.col.f32.tf32.tf32.f32 "
        "{%0,%1,%2,%3},{%4,%5,%6,%7},{%8,%9},{%0,%1,%2,%3};"
        : "+f"(d[0]), "+f"(d[1]), "+f"(d[2]), "+f"(d[3])
        : "r"(a[0]), "r"(a[1]), "r"(a[2]), "r"(a[3]), "r"(b[0]), "r"(b[1]));
}

// ---------------------------------------------------------------------------
// m32 x n32 warp-tile gemm over one k32 chunk (3xtf32).
// acc[mb][g][4]: mb in {0,1} m16-blocks, g in {0..3} n8-groups.
// B frags reused across both m-blocks; A frags across all 4 n-groups.
// ---------------------------------------------------------------------------
__device__ __forceinline__ void gemm_nk(const float* Ah, const float* Al,
                                        const float* Bh, const float* Bl,
                                        float acc[2][4][4], int wm, int wn,
                                        int lane) {
    int m0 = wm * 32, n0 = wn * 32;
#pragma unroll
    for (int k0 = 0; k0 < 32; k0 += 8) {
        unsigned ah0[4], al0[4], ah1[4], al1[4];
        ldAfrag(Ah, m0, k0, lane, ah0);
        ldAfrag(Al, m0, k0, lane, al0);
        ldAfrag(Ah, m0 + 16, k0, lane, ah1);
        ldAfrag(Al, m0 + 16, k0, lane, al1);
#pragma unroll
        for (int g = 0; g < 4; ++g) {
            unsigned bh2[2], bl2[2];
            ldBnk(Bh, n0 + 8 * g, k0, lane, bh2);
            ldBnk(Bl, n0 + 8 * g, k0, lane, bl2);
            mma8(acc[0][g], ah0, bh2);
            mma8(acc[0][g], ah0, bl2);
            mma8(acc[0][g], al0, bh2);
            mma8(acc[1][g], ah1, bh2);
            mma8(acc[1][g], ah1, bl2);
            mma8(acc[1][g], al1, bh2);
        }
    }
}

__device__ __forceinline__ void gemm_kn(const float* Ah, const float* Al,
                                        const float* Bh, const float* Bl,
                                        float acc[2][4][4], int wm, int wn,
                                        int lane) {
    int m0 = wm * 32, n0 = wn * 32;
#pragma unroll
    for (int k0 = 0; k0 < 32; k0 += 8) {
        unsigned ah0[4], al0[4], ah1[4], al1[4];
        ldAfrag(Ah, m0, k0, lane, ah0);
        ldAfrag(Al, m0, k0, lane, al0);
        ldAfrag(Ah, m0 + 16, k0, lane, ah1);
        ldAfrag(Al, m0 + 16, k0, lane, al1);
#pragma unroll
        for (int g = 0; g < 4; ++g) {
            unsigned bh2[2], bl2[2];
            ldBkn(Bh, n0 + 8 * g, k0, lane, bh2);
            ldBkn(Bl, n0 + 8 * g, k0, lane, bl2);
            mma8(acc[0][g], ah0, bh2);
            mma8(acc[0][g], ah0, bl2);
            mma8(acc[0][g], al0, bh2);
            mma8(acc[1][g], ah1, bh2);
            mma8(acc[1][g], ah1, bl2);
            mma8(acc[1][g], al1, bh2);
        }
    }
}

// ---------------------------------------------------------------------------
__global__ __launch_bounds__(256) void k_pack(const float* __restrict__ q) {
    int i = blockIdx.x, tid = threadIdx.x;
#pragma unroll
    for (int p = 0; p < 4; ++p) {
        int idx = tid + p * 256;
        int bh = idx >> 4, c4 = idx & 15;
        float4 v = *(const float4*)(q + ((size_t)bh * QN + i) * DN + c4 * 4);
        v.x *= QSCALE; v.y *= QSCALE; v.z *= QSCALE; v.w *= QSCALE;
        *(float4*)(g_qp + (size_t)i * (BHN * DN) + bh * DN + c4 * 4) = v;
    }
}

// ---------------------------------------------------------------------------
// G1: score = q_s . k  (136 causal tiles per bh) — 128 thr, 4 warps m32n32
// ---------------------------------------------------------------------------
__global__ __launch_bounds__(128) void k_score_qk(const float* __restrict__ q,
                                                  const float* __restrict__ kk,
                                                  float* __restrict__ alpha) {
    int ti, tj;
    tri_decode(blockIdx.x, ti, tj);
    int bh = blockIdx.y;
    __shared__ alignas(16) float Ah[64 * LA], Al[64 * LA];
    __shared__ alignas(16) float Bh[64 * LA], Bl[64 * LA];
    int tid = threadIdx.x, lane = tid & 31, w = tid >> 5;
    int wm = w & 1, wn = w >> 1;
    float acc[2][4][4] = {};
#pragma unroll
    for (int kc = 0; kc < 2; ++kc) {
        fillA(Ah, Al, q + ((size_t)bh * QN + ti * 64) * DN + kc * 32, DN, QSCALE, tid);
        fillA(Bh, Bl, kk + ((size_t)bh * KN + tj * 64) * DN + kc * 32, DN, 1.f, tid);
        __syncthreads();
        gemm_nk(Ah, Al, Bh, Bl, acc, wm, wn, lane);
        __syncthreads();
    }
    float* base = alpha + (size_t)bh * QN * KN;
    int c0 = tj * 64 + wn * 32 + 2 * (lane & 3);
#pragma unroll
    for (int mb = 0; mb < 2; ++mb) {
        int r0 = ti * 64 + wm * 32 + mb * 16 + (lane >> 2);
#pragma unroll
        for (int g = 0; g < 4; ++g) {
            *(float2*)(base + (size_t)r0 * KN + c0 + 8 * g) =
                make_float2(acc[mb][g][0], acc[mb][g][1]);
            *(float2*)(base + (size_t)(r0 + 8) * KN + c0 + 8 * g) =
                make_float2(acc[mb][g][2], acc[mb][g][3]);
        }
    }
}

// ---------------------------------------------------------------------------
// G2: score += q_s . rpe_q[i]  (per-i GEMM over bh; live tiles only)
// ---------------------------------------------------------------------------
__global__ __launch_bounds__(128) void k_score_rpe(const float* __restrict__ rq,
                                                   float* __restrict__ alpha) {
    int t = blockIdx.x;
    int gi, tj;
    tri_decode(t >> 6, gi, tj);
    int i = gi * 64 + (t & 63);
    __shared__ alignas(16) float Ah[64 * LA], Al[64 * LA];
    __shared__ alignas(16) float Bh[64 * LA], Bl[64 * LA];
    int tid = threadIdx.x, lane = tid & 31, w = tid >> 5;
    int wm = w & 1, wn = w >> 1;
    float acc[2][4][4] = {};
#pragma unroll
    for (int kc = 0; kc < 2; ++kc) {
        fillA(Ah, Al, g_qp + (size_t)i * (BHN * DN) + kc * 32, DN, 1.f, tid);
        fillA(Bh, Bl, rq + ((size_t)i * KN + tj * 64) * DN + kc * 32, DN, 1.f, tid);
        __syncthreads();
        gemm_nk(Ah, Al, Bh, Bl, acc, wm, wn, lane);
        __syncthreads();
    }
    int j0 = tj * 64 + wn * 32 + 2 * (lane & 3);
#pragma unroll
    for (int mb = 0; mb < 2; ++mb) {
        int bh0 = wm * 32 + mb * 16 + (lane >> 2);
#pragma unroll
        for (int g = 0; g < 4; ++g) {
            float2* p0 = (float2*)(alpha + ((size_t)bh0 * QN + i) * KN + j0 + 8 * g);
            float2* p1 = (float2*)(alpha + ((size_t)(bh0 + 8) * QN + i) * KN + j0 + 8 * g);
            float2 v0 = *p0, v1 = *p1;
            v0.x += acc[mb][g][0]; v0.y += acc[mb][g][1];
            v1.x += acc[mb][g][2]; v1.y += acc[mb][g][3];
            *p0 = v0; *p1 = v1;
        }
    }
}

// ---------------------------------------------------------------------------
// softmax: warp-per-row, causal, fully unrolled register pipeline.
// ---------------------------------------------------------------------------
__global__ __launch_bounds__(256) void k_softmax(float* __restrict__ alpha) {
    int bh = blockIdx.x;
    int i = blockIdx.y * 8 + (threadIdx.x >> 5);
    int lane = threadIdx.x & 31;
    float4* row = (float4*)(alpha + ((size_t)bh * QN + i) * KN);

    int nq4 = (i >> 2) + 1;

    float4 e[8];
    float vmax = -INFINITY;
#pragma unroll
    for (int it = 0; it < 8; ++it) {
        int j4 = lane + it * 32;
        float4 s = make_float4(-INFINITY, -INFINITY, -INFINITY, -INFINITY);
        if (j4 < nq4) {
            s = row[j4];
            int j = j4 * 4;
            if (j + 1 > i) s.y = -INFINITY;
            if (j + 2 > i) s.z = -INFINITY;
            if (j + 3 > i) s.w = -INFINITY;
        }
        e[it] = s;
        vmax = fmaxf(vmax, fmaxf(fmaxf(s.x, s.y), fmaxf(s.z, s.w)));
    }
#pragma unroll
    for (int o = 16; o > 0; o >>= 1)
        vmax = fmaxf(vmax, __shfl_xor_sync(0xffffffffu, vmax, o));

    float lsum = 0.f;
#pragma unroll
    for (int it = 0; it < 8; ++it) {
        float4 s = e[it];
        float4 ev;
        ev.x = (s.x == -INFINITY) ? 0.f : __expf(s.x - vmax);
        ev.y = (s.y == -INFINITY) ? 0.f : __expf(s.y - vmax);
        ev.z = (s.z == -INFINITY) ? 0.f : __expf(s.z - vmax);
        ev.w = (s.w == -INFINITY) ? 0.f : __expf(s.w - vmax);
        e[it] = ev;
        lsum += ev.x + ev.y + ev.z + ev.w;
    }
#pragma unroll
    for (int o = 16; o > 0; o >>= 1)
        lsum += __shfl_xor_sync(0xffffffffu, lsum, o);
    float inv = (lsum > 0.f) ? (1.f / lsum) : 0.f;

#pragma unroll
    for (int it = 0; it < 8; ++it) {
        int j4 = lane + it * 32;
        float4 ev = e[it];
        row[j4] = make_float4(ev.x * inv, ev.y * inv, ev.z * inv, ev.w * inv);
    }
}

// ---------------------------------------------------------------------------
// G3: ctx = alpha @ v   (per (ti,bh); causal k-loop in 32-chunks)
// ---------------------------------------------------------------------------
__global__ __launch_bounds__(128) void k_ctx_v(const float* __restrict__ alpha,
                                               const float* __restrict__ v,
                                               float* __restrict__ ctx) {
    int ti = blockIdx.x, bh = blockIdx.y;
    __shared__ alignas(16) float Ah[64 * LA], Al[64 * LA];
    __shared__ alignas(16) float Bh[32 * LB], Bl[32 * LB];
    int tid = threadIdx.x, lane = tid & 31, w = tid >> 5;
    int wm = w & 1, wn = w >> 1;
    float acc[2][4][4] = {};
    int nch = (ti + 1) * 2;
    for (int kc = 0; kc < nch; ++kc) {
        fillA(Ah, Al, alpha + ((size_t)bh * QN + ti * 64) * KN + kc * 32, KN, 1.f, tid);
        fillB(Bh, Bl, v + ((size_t)bh * KN + kc * 32) * DN, DN, tid);
        __syncthreads();
        gemm_kn(Ah, Al, Bh, Bl, acc, wm, wn, lane);
        __syncthreads();
    }
    float* base = ctx + (size_t)bh * QN * DN;
    int c0 = wn * 32 + 2 * (lane & 3);
#pragma unroll
    for (int mb = 0; mb < 2; ++mb) {
        int r0 = ti * 64 + wm * 32 + mb * 16 + (lane >> 2);
#pragma unroll
        for (int g = 0; g < 4; ++g) {
            *(float2*)(base + (size_t)r0 * DN + c0 + 8 * g) =
                make_float2(acc[mb][g][0], acc[mb][g][1]);
            *(float2*)(base + (size_t)(r0 + 8) * DN + c0 + 8 * g) =
                make_float2(acc[mb][g][2], acc[mb][g][3]);
        }
    }
}

// ---------------------------------------------------------------------------
// G4: ctx[bh,i,:] += sum_j alpha[bh,i,j] * rpe_v[i,j,:]  (per-i over bh)
// ---------------------------------------------------------------------------
__global__ __launch_bounds__(128) void k_ctx_rpe(const float* __restrict__ alpha,
                                                 const float* __restrict__ rv,
                                                 float* __restrict__ ctx) {
    int i = (QN - 1) - blockIdx.x;
    int nch = (i >> 5) + 1;
    __shared__ alignas(16) float Ah[64 * LA], Al[64 * LA];
    __shared__ alignas(16) float Bh[32 * LB], Bl[32 * LB];
    int tid = threadIdx.x, lane = tid & 31, w = tid >> 5;
    int wm = w & 1, wn = w >> 1;
    float acc[2][4][4] = {};
    for (int kc = 0; kc < nch; ++kc) {
        fillA(Ah, Al, alpha + (size_t)i * KN + kc * 32, (size_t)QN * KN, 1.f, tid);
        fillB(Bh, Bl, rv + ((size_t)i * KN + kc * 32) * DN, DN, tid);
        __syncthreads();
        gemm_kn(Ah, Al, Bh, Bl, acc, wm, wn, lane);
        __syncthreads();
    }
    int c0 = wn * 32 + 2 * (lane & 3);
#pragma unroll
    for (int mb = 0; mb < 2; ++mb) {
        int bh0 = wm * 32 + mb * 16 + (lane >> 2);
#pragma unroll
        for (int g = 0; g < 4; ++g) {
            float2* p0 = (float2*)(ctx + ((size_t)bh0 * QN + i) * DN + c0 + 8 * g);
            float2* p1 = (float2*)(ctx + ((size_t)(bh0 + 8) * QN + i) * DN + c0 + 8 * g);
            float2 v0 = *p0, v1 = *p1;
            v0.x += acc[mb][g][0]; v0.y += acc[mb][g][1];
            v1.x += acc[mb][g][2]; v1.y += acc[mb][g][3];
            *p0 = v0; *p1 = v1;
        }
    }
}

// ---------------------------------------------------------------------------
extern "C" void kernel_launch(void* const* d_in, const int* in_sizes, int n_in,
                              void* d_out, int out_size) {
    const float* q    = (const float*)d_in[0];
    const float* kk   = (const float*)d_in[1];
    const float* v    = (const float*)d_in[2];
    const float* rq   = (const float*)d_in[4];
    const float* rv   = (const float*)d_in[5];

    float* ctx   = (float*)d_out;
    float* alpha = ctx + (size_t)BHN * QN * DN;

    k_pack<<<QN, 256>>>(q);
    k_score_qk<<<dim3(136, BHN), 128>>>(q, kk, alpha);
    k_score_rpe<<<136 * 64, 128>>>(rq, alpha);
    k_softmax<<<dim3(BHN, QN / 8), 256>>>(alpha);
    k_ctx_v<<<dim3(16, BHN), 128>>>(alpha, v, ctx);
    k_ctx_rpe<<<QN, 128>>>(alpha, rv, ctx);
}